// round 12
// baseline (speedup 1.0000x reference)
#include <cuda_runtime.h>
#include <cuda_bf16.h>
#include <cstdint>

// MatrixExpander: out(16,16,512,512) = kron(A(16,16,64,64), ones(8,8)), fp32.
//
// R12: warp-autonomous variant of the R7 floor-sitter (43.5us bench,
// 6.7 TB/s write ~= 97% of the path-independent LTS write-ingress cap).
// Removes the last two non-floor costs of R7:
//   - no __syncthreads: each warp fills ONE 2 KB output row of the tile and
//     issues its own 2 KB cp.async.bulk after only a __syncwarp
//   - 8 issuing lanes per CTA instead of 1 -> stores start at each warp's
//     own earliest moment, not the slowest warp's
//
// Tile c in [0,16384): out[c*4096 .. +4096) = 8 copies of the expanded row
// expanded[j] = A[c*64 + j/8]. Warp w owns copy w (smem row[w], 128 float4).
//
// Conflict-free fill: lane l writes slots {l, l+32, l+64, l+96} of its row
// (16 B lane stride). Slot 32k+l needs A col (32k+l)>>1 = 16k + (l>>1):
// four scalar loads per lane, all adjacent-thread broadcasts from one 256 B
// A row (L1/L2 hits; A is L2-resident).

__device__ __forceinline__ uint32_t smem_u32(const void* p) {
    uint32_t a;
    asm("{ .reg .u64 t; cvta.to.shared.u64 t, %1; cvt.u32.u64 %0, t; }"
        : "=r"(a) : "l"(p));
    return a;
}

__global__ __launch_bounds__(256)
void expander_tma_r12_kernel(const float* __restrict__ A, float* __restrict__ out)
{
    __shared__ __align__(128) float4 buf[8][128];   // 8 x 2 KB rows = 16 KB

    const uint32_t c    = blockIdx.x;          // tile id [0, 16384)
    const uint32_t w    = threadIdx.x >> 5;    // warp [0, 8)
    const uint32_t l    = threadIdx.x & 31u;   // lane

    const float* arow = A + (c << 6);
    const uint32_t cofs = l >> 1;              // [0, 16)

    const float v0 = __ldg(arow + cofs);
    const float v1 = __ldg(arow + 16u + cofs);
    const float v2 = __ldg(arow + 32u + cofs);
    const float v3 = __ldg(arow + 48u + cofs);

    float4* b = buf[w];
    b[l      ] = make_float4(v0, v0, v0, v0);
    b[l + 32u] = make_float4(v1, v1, v1, v1);
    b[l + 64u] = make_float4(v2, v2, v2, v2);
    b[l + 96u] = make_float4(v3, v3, v3, v3);

    __syncwarp();

    if (l == 0) {
        // Order this warp's generic-proxy STS before its async-proxy read.
        asm volatile("fence.proxy.async.shared::cta;" ::: "memory");
        const uint32_t s = smem_u32(b);
        const float* dst = out + ((size_t)c << 12) + (w << 9);  // row w of tile
        asm volatile(
            "cp.async.bulk.global.shared::cta.bulk_group [%0], [%1], %2;"
            :: "l"(dst), "r"(s), "n"(2048) : "memory");
        asm volatile("cp.async.bulk.commit_group;" ::: "memory");
        asm volatile("cp.async.bulk.wait_group 0;" ::: "memory");
    }
}

extern "C" void kernel_launch(void* const* d_in, const int* in_sizes, int n_in,
                              void* d_out, int out_size)
{
    const float* A = (const float*)d_in[0];   // (16,16,64,64) fp32
    float* out = (float*)d_out;               // (16,16,512,512) fp32

    // 16384 tiles x 8 warp-stores x 2 KB = 256 MiB output
    expander_tma_r12_kernel<<<16384, 256>>>(A, out);
}

// round 13
// speedup vs baseline: 1.0059x; 1.0059x over previous
#include <cuda_runtime.h>
#include <cuda_bf16.h>
#include <cstdint>

// MatrixExpander: out(16,16,512,512) = kron(A(16,16,64,64), ones(8,8)), fp32.
//
// FINAL (R7): best reproducible bench 43.49us (x2), kernel 40.0-40.8us
// = 6.6-6.7 TB/s effective write, ~97% of the path-independent SM->LTS
// write-ingress cap (~6300 B/cyc). 268 MB must cross LTS once; this is the
// chip roofline for the problem.
//
// Design: one CTA per tile. Tile c in [0,16384) covers out[c*4096 .. +4096)
// (16 KB contiguous) = 8 copies of the 512-float expanded row of A-row c,
// expanded[j] = A[c*64 + j/8]. Build the 16 KB tile in smem with a
// conflict-free fill, push with ONE cp.async.bulk store. One-shot CTA swarm
// is the pipelining mechanism (scheduler overlaps fills against in-flight
// bulk stores of retiring CTAs).
//
// Dead alternatives (R1-R12, all measured): plain STG 5.0 TB/s; STG/TMA
// hybrids <=6.2; persistent double-buffered CTAs -10%; 2-tile CTAs -1.5%;
// 8x smem-source reuse = equal kernel, worse bench; stride-128B fill -45%;
// __stcs -15%; warp-autonomous 8x2KB stores = equal kernel, +0.3us bench.
//
// Fill layout: thread t writes float4 slots {t, t+256, t+512, t+768}:
//   - 16 B lane stride -> fully coalesced, zero bank conflicts
//   - all four slots need the SAME A col (t & 127) >> 1 -> one scalar load
//     (adjacent-thread broadcast), one splat, 4 STS.128.

__device__ __forceinline__ uint32_t smem_u32(const void* p) {
    uint32_t a;
    asm("{ .reg .u64 t; cvta.to.shared.u64 t, %1; cvt.u32.u64 %0, t; }"
        : "=r"(a) : "l"(p));
    return a;
}

__global__ __launch_bounds__(256)
void expander_tma_kernel(const float* __restrict__ A, float* __restrict__ out)
{
    __shared__ __align__(128) float4 buf[1024];   // 16 KB = 8 output rows

    const uint32_t c = blockIdx.x;   // tile id in [0, 16384)
    const uint32_t t = threadIdx.x;  // [0, 256)

    // One A value per thread (pairs of adjacent threads share -> broadcast).
    const float v = __ldg(A + (c << 6) + ((t & 127u) >> 1));
    const float4 v4 = make_float4(v, v, v, v);

    buf[t        ] = v4;
    buf[t + 256u ] = v4;
    buf[t + 512u ] = v4;
    buf[t + 768u ] = v4;

    __syncthreads();

    if (t == 0) {
        // Order generic-proxy STS before async-proxy bulk read.
        asm volatile("fence.proxy.async.shared::cta;" ::: "memory");
        const uint32_t s = smem_u32(buf);
        const float* dst = out + ((size_t)c << 12);   // c * 16 KB
        asm volatile(
            "cp.async.bulk.global.shared::cta.bulk_group [%0], [%1], %2;"
            :: "l"(dst), "r"(s), "n"(16384) : "memory");
        asm volatile("cp.async.bulk.commit_group;" ::: "memory");
        asm volatile("cp.async.bulk.wait_group 0;" ::: "memory");
    }
}

extern "C" void kernel_launch(void* const* d_in, const int* in_sizes, int n_in,
                              void* d_out, int out_size)
{
    const float* A = (const float*)d_in[0];   // (16,16,64,64) fp32
    float* out = (float*)d_out;               // (16,16,512,512) fp32

    // 16384 tiles x 16 KB = 256 MiB output
    expander_tma_kernel<<<16384, 256>>>(A, out);
}